// round 13
// baseline (speedup 1.0000x reference)
#include <cuda_runtime.h>
#include <cuda.h>
#include <cstdint>

#define NMAX 50000
#define RK 300
#define TILE 64

__device__ float g_h[NMAX * 64];
__device__ float g_agg[NMAX * 64];
// fw1 frags: [cs][qn][lane] -> (b0_t, b1_t, b0_t1, b1_t1); k=8cs+t4(+4), n=16qn+g4(+8)
__device__ float4 g_fw1q[40 * 4 * 32];
__device__ float4 g_fw2q[8 * 4 * 32];
__device__ int g_is64;

__device__ __forceinline__ float sspf(float x) {
    float t = __expf(-fabsf(x));
    return fmaxf(x, 0.f) + __logf(1.f + t) - 0.69314718055994531f;
}
__device__ __forceinline__ uint32_t cvt_tf32(float x) {
    uint32_t r; asm("cvt.rna.tf32.f32 %0, %1;" : "=r"(r) : "f"(x)); return r;
}
__device__ __forceinline__ float tf32r(float x) { return __uint_as_float(cvt_tf32(x)); }

__device__ __forceinline__ void mma_tf32(float d[4], uint32_t a0, uint32_t a1,
                                         uint32_t a2, uint32_t a3,
                                         uint32_t b0, uint32_t b1) {
    asm volatile(
        "mma.sync.aligned.m16n8k8.row.col.f32.tf32.tf32.f32 "
        "{%0,%1,%2,%3}, {%4,%5,%6,%7}, {%8,%9}, {%0,%1,%2,%3};"
        : "+f"(d[0]), "+f"(d[1]), "+f"(d[2]), "+f"(d[3])
        : "r"(a0), "r"(a1), "r"(a2), "r"(a3), "r"(b0), "r"(b1));
}
__device__ __forceinline__ void cp16(uint32_t saddr, const void* g, int sz) {
    asm volatile("cp.async.cg.shared.global [%0], [%1], 16, %2;"
                 :: "r"(saddr), "l"(g), "r"(sz));
}
__device__ __forceinline__ void cp_commit() { asm volatile("cp.async.commit_group;"); }
__device__ __forceinline__ void cp_wait0()  { asm volatile("cp.async.wait_group 0;"); }

__device__ __forceinline__ void bulk_g2s(uint32_t dst, const void* src, int bytes,
                                         uint32_t mbar) {
    asm volatile(
        "cp.async.bulk.shared::cta.global.mbarrier::complete_tx::bytes [%0], [%1], %2, [%3];"
        :: "r"(dst), "l"(src), "r"(bytes), "r"(mbar) : "memory");
}
__device__ __forceinline__ void mbar_init(uint32_t a, uint32_t cnt) {
    asm volatile("mbarrier.init.shared.b64 [%0], %1;" :: "r"(a), "r"(cnt) : "memory");
}
__device__ __forceinline__ void mbar_expect(uint32_t a, uint32_t tx) {
    asm volatile("mbarrier.arrive.expect_tx.shared.b64 _, [%0], %1;"
                 :: "r"(a), "r"(tx) : "memory");
}
__device__ __forceinline__ void mbar_wait(uint32_t a, uint32_t ph) {
    uint32_t done = 0;
    do {
        asm volatile(
            "{\n\t.reg .pred p;\n\t"
            "mbarrier.try_wait.parity.acquire.cta.shared::cta.b64 p, [%1], %2, 0x989680;\n\t"
            "selp.b32 %0, 1, 0, p;\n\t}"
            : "=r"(done) : "r"(a), "r"(ph) : "memory");
    } while (!done);
}

__global__ void detect_idx_kernel(const int* __restrict__ ei32) {
    if (threadIdx.x == 0 && blockIdx.x == 0) {
        int ornz = 0;
#pragma unroll
        for (int i = 0; i < 64; ++i) ornz |= ei32[2 * i + 1];
        g_is64 = (ornz == 0) ? 1 : 0;
    }
}

// fragment-major tf32 weights, N split in 16-col quarters (qn).
__global__ void prep_frag_kernel(const float* __restrict__ fw1,
                                 const float* __restrict__ fw2) {
    int i = blockIdx.x * blockDim.x + threadIdx.x;
    if (i < 40 * 4 * 32) {
        int lane = i & 31, qn = (i >> 5) & 3, cs = i >> 7;
        int t4 = lane & 3, g4 = lane >> 2;
        int k = 8 * cs + t4;
        int n0 = 16 * qn + g4, n1 = n0 + 8;
        float4 q;
        q.x = (k < RK) ? tf32r(fw1[k * 64 + n0]) : 0.f;
        q.y = (k + 4 < RK) ? tf32r(fw1[(k + 4) * 64 + n0]) : 0.f;
        q.z = (k < RK) ? tf32r(fw1[k * 64 + n1]) : 0.f;
        q.w = (k + 4 < RK) ? tf32r(fw1[(k + 4) * 64 + n1]) : 0.f;
        g_fw1q[i] = q;
    }
    if (i < 8 * 4 * 32) {
        int lane = i & 31, qn = (i >> 5) & 3, s = i >> 7;
        int t4 = lane & 3, g4 = lane >> 2;
        int k = 8 * s + t4;
        int n0 = 16 * qn + g4, n1 = n0 + 8;
        float4 q;
        q.x = tf32r(fw2[k * 64 + n0]);
        q.y = tf32r(fw2[(k + 4) * 64 + n0]);
        q.z = tf32r(fw2[k * 64 + n1]);
        q.w = tf32r(fw2[(k + 4) * 64 + n1]);
        g_fw2q[i] = q;
    }
}

// ---------------------------------------------------------------------------
// node kernels (proven R6 versions)
// ---------------------------------------------------------------------------
__global__ void __launch_bounds__(256)
node_pre_kernel(const float* __restrict__ x, const float* __restrict__ W,
                const float* __restrict__ b, int N) {
    __shared__ float xs[128 * 64];
    int tid = threadIdx.x;
    int j = tid & 63, q = tid >> 6;
    long n0 = (long)blockIdx.x * 128;
    uint32_t sb = (uint32_t)__cvta_generic_to_shared(xs);
    for (int i = tid; i < 2048; i += 256) {
        long node = n0 + (i >> 4);
        cp16(sb + i * 16, x + node * 64 + (i & 15) * 4, node < N ? 16 : 0);
    }
    cp_commit();
    float Wc[64];
#pragma unroll
    for (int k = 0; k < 64; ++k) Wc[k] = W[k * 64 + j];
    float bj = b[j];
    cp_wait0();
    __syncthreads();
#pragma unroll 4
    for (int nn = 0; nn < 32; ++nn) {
        int r = nn * 4 + q;
        long node = n0 + r;
        float acc = bj;
        const float* xr = xs + r * 64;
#pragma unroll
        for (int k = 0; k < 64; k += 4) {
            float4 xv = *(const float4*)(xr + k);
            acc += xv.x * Wc[k] + xv.y * Wc[k + 1] + xv.z * Wc[k + 2] + xv.w * Wc[k + 3];
        }
        if (node < N) {
            g_h[node * 64 + j] = acc;
            g_agg[node * 64 + j] = 0.f;
        }
    }
}

__global__ void __launch_bounds__(256)
node_post_kernel(const float* __restrict__ x0, const float* __restrict__ W2,
                 const float* __restrict__ b2, const float* __restrict__ W3,
                 const float* __restrict__ b3, float* __restrict__ out, int N) {
    extern __shared__ float smp[];
    float* xs = smp;
    float* ts = smp + 8192;
    int tid = threadIdx.x;
    int j = tid & 63, q = tid >> 6;
    long n0 = (long)blockIdx.x * 128;
    uint32_t sb = (uint32_t)__cvta_generic_to_shared(xs);
    for (int i = tid; i < 2048; i += 256) {
        long node = n0 + (i >> 4);
        cp16(sb + i * 16, g_agg + node * 64 + (i & 15) * 4, node < N ? 16 : 0);
    }
    cp_commit();
    float W2c[64], W3c[64];
#pragma unroll
    for (int k = 0; k < 64; ++k) { W2c[k] = W2[k * 64 + j]; W3c[k] = W3[k * 64 + j]; }
    float b2j = b2[j], b3j = b3[j];
    cp_wait0();
    __syncthreads();
#pragma unroll 4
    for (int nn = 0; nn < 32; ++nn) {
        int r = nn * 4 + q;
        float acc = b2j;
        const float* xr = xs + r * 64;
#pragma unroll
        for (int k = 0; k < 64; k += 4) {
            float4 xv = *(const float4*)(xr + k);
            acc += xv.x * W2c[k] + xv.y * W2c[k + 1] + xv.z * W2c[k + 2] + xv.w * W2c[k + 3];
        }
        ts[r * 64 + j] = sspf(acc);
    }
    __syncthreads();
#pragma unroll 4
    for (int nn = 0; nn < 32; ++nn) {
        int r = nn * 4 + q;
        long node = n0 + r;
        float acc = b3j;
        const float* tr = ts + r * 64;
#pragma unroll
        for (int k = 0; k < 64; k += 4) {
            float4 tv = *(const float4*)(tr + k);
            acc += tv.x * W3c[k] + tv.y * W3c[k + 1] + tv.z * W3c[k + 2] + tv.w * W3c[k + 3];
        }
        if (node < N) out[node * 64 + j] = acc + x0[node * 64 + j];
    }
}

// ---------------------------------------------------------------------------
// edge kernel: TILE=64 so smem ~94KB -> fw1/fw2 frag tables (96KB) fit L1D.
// All streaming traffic (.cg) bypasses L1. 16 warps: 4 rowgroups x 4 N-quarters.
// ---------------------------------------------------------------------------
#define OFF_A   0        // 64 rows x 300 floats = 19200 (75KB)
#define OFF_PAD 19200    // 32 floats zero pad (k-tail overreads)
#define OFF_C   19232    // 64 x 64 = 4096 (16KB)
#define OFF_B1  23328
#define OFF_B2  23392
#define OFF_MB  23456    // 2 mbarriers
#define SMEM_FLOATS 23460
#define CSW(r, c) ((r) * 64 + ((c) ^ (((r) & 7) << 2)))
#define FU(x) __float_as_uint(x)

__global__ void __launch_bounds__(512)
edge_kernel(const float* __restrict__ rbf, const void* __restrict__ ei,
            const float* __restrict__ dist, const float* __restrict__ cutoff,
            const float* __restrict__ fb1, const float* __restrict__ fb2,
            int E, int NT, int GRIDSZ) {
    extern __shared__ __align__(1024) float sm[];
    uint32_t sbase = (uint32_t)__cvta_generic_to_shared(sm);
    int tid = threadIdx.x, lane = tid & 31, warp = tid >> 5;
    int t4 = lane & 3, g4 = lane >> 2;
    int qn = warp & 3, rg = warp >> 2, rw = rg * 16;
    uint32_t mb0 = sbase + OFF_MB * 4, mb1 = mb0 + 8;
    uint32_t mymb = (rg >= 2) ? mb1 : mb0;

    // zero A + pad once (stale-tail-proof), biases, mbarriers
    for (int i = tid; i < 19232; i += 512) sm[i] = 0.f;
    if (tid < 64) { sm[OFF_B1 + tid] = fb1[tid]; sm[OFF_B2 + tid] = fb2[tid]; }
    if (tid == 0) { mbar_init(mb0, 1); mbar_init(mb1, 1); }
    __syncthreads();

    int is64 = g_is64;
    float picf = 3.14159265f / (*cutoff);

    auto issue = [&](long t) {
        if (t >= (long)NT) return;
        long e0 = t * TILE;
        int V = (int)((long)E - e0 < TILE ? (long)E - e0 : TILE);
        int V0 = V < 32 ? V : 32;
        int V1 = V - V0;
        mbar_expect(mb0, (uint32_t)(V0 * 1200));
        bulk_g2s(sbase + OFF_A * 4, rbf + e0 * 300, V0 * 1200, mb0);
        mbar_expect(mb1, (uint32_t)(V1 * 1200));
        if (V1 > 0)
            bulk_g2s(sbase + (OFF_A + 32 * 300) * 4, rbf + (e0 + 32) * 300,
                     V1 * 1200, mb1);
    };
    if (tid == 0) issue(blockIdx.x);
    int ph = 0;

    int el = tid >> 3, oc = tid & 7;

    for (long tile = blockIdx.x; tile < (long)NT; tile += GRIDSZ) {
        long e0 = tile * TILE;

        // epilogue index/dist preload via .cg (L2-only, keeps L1 for weights)
        long e = e0 + el;
        long long dstn = 0, srcn = 0;
        float f = 0.f;
        if (e < (long)E) {
            if (is64) {
                const long long* pp = (const long long*)ei;
                dstn = __ldcg(pp + e); srcn = __ldcg(pp + (long)E + e);
            } else {
                const int* pp = (const int*)ei;
                dstn = __ldcg(pp + e); srcn = __ldcg(pp + (long)E + e);
            }
            dstn = dstn < 0 ? 0 : (dstn >= NMAX ? NMAX - 1 : dstn);
            srcn = srcn < 0 ? 0 : (srcn >= NMAX ? NMAX - 1 : srcn);
            f = 1.f + __cosf(picf * __ldcg(dist + e));
        }

        // ---- GEMM1: K fully resident, single wait per warp ----
        mbar_wait(mymb, ph);
        float acc[2][4];
#pragma unroll
        for (int t = 0; t < 2; ++t)
#pragma unroll
            for (int jj = 0; jj < 4; ++jj) acc[t][jj] = 0.f;

        const float* A0 = sm + OFF_A + (rw + g4) * 300 + t4;
        const float* A1 = A0 + 8 * 300;
        const float4* B1 = g_fw1q + qn * 32 + lane;
        float4 qa = __ldg(B1), qb = __ldg(B1 + 128);
#pragma unroll 4
        for (int cs = 0; cs < 40; ++cs) {
            float4 qc;
            if (cs < 38) qc = __ldg(B1 + (cs + 2) * 128);
            uint32_t a0 = FU(A0[8 * cs]);
            uint32_t a1 = FU(A1[8 * cs]);
            uint32_t a2 = FU(A0[8 * cs + 4]);
            uint32_t a3 = FU(A1[8 * cs + 4]);
            mma_tf32(acc[0], a0, a1, a2, a3, FU(qa.x), FU(qa.y));
            mma_tf32(acc[1], a0, a1, a2, a3, FU(qa.z), FU(qa.w));
            qa = qb; qb = qc;
        }

        // bias + ssp -> stage C1 (swizzled)
#pragma unroll
        for (int tl = 0; tl < 2; ++tl) {
            int cb = 16 * qn + 8 * tl + 2 * t4;
            float b0v = sm[OFF_B1 + cb], b1v = sm[OFF_B1 + cb + 1];
            *(float2*)&sm[OFF_C + CSW(rw + g4, cb)] =
                make_float2(sspf(acc[tl][0] + b0v), sspf(acc[tl][1] + b1v));
            *(float2*)&sm[OFF_C + CSW(rw + g4 + 8, cb)] =
                make_float2(sspf(acc[tl][2] + b0v), sspf(acc[tl][3] + b1v));
        }
        __syncthreads();                      // (1) C1 complete; A consumed

        if (tid == 0) issue(tile + GRIDSZ);   // next tile's sequential bulks

        // ---- GEMM2: A-frags (full K=64) from C1 ----
        float af[8][4];
#pragma unroll
        for (int s = 0; s < 8; ++s) {
            int col = 8 * s + t4;
            af[s][0] = sm[OFF_C + CSW(rw + g4, col)];
            af[s][1] = sm[OFF_C + CSW(rw + g4 + 8, col)];
            af[s][2] = sm[OFF_C + CSW(rw + g4, col + 4)];
            af[s][3] = sm[OFF_C + CSW(rw + g4 + 8, col + 4)];
        }
        __syncthreads();                      // (2) reads done before overwrite

        float acc2[2][4];
#pragma unroll
        for (int t = 0; t < 2; ++t)
#pragma unroll
            for (int jj = 0; jj < 4; ++jj) acc2[t][jj] = 0.f;
        const float4* B2 = g_fw2q + qn * 32 + lane;
#pragma unroll
        for (int s = 0; s < 8; ++s) {
            float4 q = __ldg(B2 + s * 128);
            uint32_t a0 = FU(af[s][0]), a1 = FU(af[s][1]);
            uint32_t a2 = FU(af[s][2]), a3 = FU(af[s][3]);
            mma_tf32(acc2[0], a0, a1, a2, a3, FU(q.x), FU(q.y));
            mma_tf32(acc2[1], a0, a1, a2, a3, FU(q.z), FU(q.w));
        }

        // bias + ssp -> w2 into C
#pragma unroll
        for (int tl = 0; tl < 2; ++tl) {
            int cb = 16 * qn + 8 * tl + 2 * t4;
            float b0v = sm[OFF_B2 + cb], b1v = sm[OFF_B2 + cb + 1];
            *(float2*)&sm[OFF_C + CSW(rw + g4, cb)] =
                make_float2(sspf(acc2[tl][0] + b0v), sspf(acc2[tl][1] + b1v));
            *(float2*)&sm[OFF_C + CSW(rw + g4 + 8, cb)] =
                make_float2(sspf(acc2[tl][2] + b0v), sspf(acc2[tl][3] + b1v));
        }
        __syncthreads();                      // (3) w2 ready

        // epilogue: gather h[src] (.cg), scatter atomics into agg[dst]
        if (e < (long)E) {
            const float* hrow = g_h + (long)srcn * 64 + oc * 8;
            float* arow = g_agg + (long)dstn * 64 + oc * 8;
#pragma unroll
            for (int jj = 0; jj < 2; ++jj) {
                float4 w = *(const float4*)&sm[OFF_C + CSW(el, oc * 8 + 4 * jj)];
                float4 h4 = __ldcg((const float4*)(hrow + 4 * jj));
                atomicAdd((float4*)(arow + 4 * jj),
                          make_float4(w.x * h4.x * f, w.y * h4.y * f,
                                      w.z * h4.z * f, w.w * h4.w * f));
            }
        }
        __syncthreads();                      // (4) C free for next staging
        ph ^= 1;
    }
}

// ---------------------------------------------------------------------------
extern "C" void kernel_launch(void* const* d_in, const int* in_sizes, int n_in,
                              void* d_out, int out_size) {
    const void* ei       = d_in[0];
    const float* x       = (const float*)d_in[1];
    const float* rbf     = (const float*)d_in[2];
    const float* dist    = (const float*)d_in[3];
    const float* cutoff  = (const float*)d_in[4];
    const float* fw1     = (const float*)d_in[5];
    const float* fb1     = (const float*)d_in[6];
    const float* fw2     = (const float*)d_in[7];
    const float* fb2     = (const float*)d_in[8];
    const float* l1w     = (const float*)d_in[9];
    const float* l1b     = (const float*)d_in[10];
    const float* l2w     = (const float*)d_in[11];
    const float* l2b     = (const float*)d_in[12];
    const float* l3w     = (const float*)d_in[13];
    const float* l3b     = (const float*)d_in[14];

    int E = in_sizes[0] / 2;
    int N = in_sizes[1] / 64;
    int NT = (E + TILE - 1) / TILE;
    int NB = (N + 127) / 128;

    static int sms = 0;
    if (!sms) cudaDeviceGetAttribute(&sms, cudaDevAttrMultiProcessorCount, 0);
    int grid = sms > 0 ? sms : 148;
    if (grid > NT) grid = NT;

    cudaFuncSetAttribute(edge_kernel, cudaFuncAttributeMaxDynamicSharedMemorySize,
                         SMEM_FLOATS * 4);
    cudaFuncSetAttribute(node_post_kernel, cudaFuncAttributeMaxDynamicSharedMemorySize,
                         65536);

    detect_idx_kernel<<<1, 32>>>((const int*)ei);
    prep_frag_kernel<<<(40 * 4 * 32 + 255) / 256, 256>>>(fw1, fw2);
    node_pre_kernel<<<NB, 256>>>(x, l1w, l1b, N);
    edge_kernel<<<grid, 512, SMEM_FLOATS * 4>>>(rbf, ei, dist, cutoff,
                                                fb1, fb2, E, NT, grid);
    node_post_kernel<<<NB, 256, 65536>>>(x, l2w, l2b, l3w, l3b, (float*)d_out, N);
}

// round 14
// speedup vs baseline: 1.7008x; 1.7008x over previous
#include <cuda_runtime.h>
#include <cuda.h>
#include <cuda_fp16.h>
#include <cstdint>

#define NMAX 50000
#define RK 300
#define TILE 128

__device__ float g_h[NMAX * 64];
__device__ float g_agg[NMAX * 64];
// fp16 B-fragment tables for m16n8k16: [cs][hn][lane] -> 4 n-tiles packed in uint4
__device__ uint4 g_fw1ha[20 * 2 * 32];
__device__ uint4 g_fw1hb[20 * 2 * 32];
__device__ uint4 g_fw2ha[4 * 2 * 32];
__device__ uint4 g_fw2hb[4 * 2 * 32];
__device__ int g_is64;

__device__ __forceinline__ float sspf(float x) {
    float t = __expf(-fabsf(x));
    return fmaxf(x, 0.f) + __logf(1.f + t) - 0.69314718055994531f;
}
__device__ __forceinline__ uint32_t pk(float lo, float hi) {
    __half2 h = __floats2half2_rn(lo, hi);
    return *(uint32_t*)&h;
}
__device__ __forceinline__ void mma_f16(float d[4], uint32_t a0, uint32_t a1,
                                        uint32_t a2, uint32_t a3,
                                        uint32_t b0, uint32_t b1) {
    asm volatile(
        "mma.sync.aligned.m16n8k16.row.col.f32.f16.f16.f32 "
        "{%0,%1,%2,%3}, {%4,%5,%6,%7}, {%8,%9}, {%0,%1,%2,%3};"
        : "+f"(d[0]), "+f"(d[1]), "+f"(d[2]), "+f"(d[3])
        : "r"(a0), "r"(a1), "r"(a2), "r"(a3), "r"(b0), "r"(b1));
}
__device__ __forceinline__ void cp16(uint32_t saddr, const void* g, int sz) {
    asm volatile("cp.async.cg.shared.global [%0], [%1], 16, %2;"
                 :: "r"(saddr), "l"(g), "r"(sz));
}
__device__ __forceinline__ void cp_commit() { asm volatile("cp.async.commit_group;"); }
__device__ __forceinline__ void cp_wait0()  { asm volatile("cp.async.wait_group 0;"); }

__device__ __forceinline__ void bulk_g2s(uint32_t dst, const void* src, int bytes,
                                         uint32_t mbar) {
    asm volatile(
        "cp.async.bulk.shared::cta.global.mbarrier::complete_tx::bytes [%0], [%1], %2, [%3];"
        :: "r"(dst), "l"(src), "r"(bytes), "r"(mbar) : "memory");
}
__device__ __forceinline__ void mbar_init(uint32_t a, uint32_t cnt) {
    asm volatile("mbarrier.init.shared.b64 [%0], %1;" :: "r"(a), "r"(cnt) : "memory");
}
__device__ __forceinline__ void mbar_expect(uint32_t a, uint32_t tx) {
    asm volatile("mbarrier.arrive.expect_tx.shared.b64 _, [%0], %1;"
                 :: "r"(a), "r"(tx) : "memory");
}
__device__ __forceinline__ void mbar_wait(uint32_t a, uint32_t ph) {
    uint32_t done = 0;
    do {
        asm volatile(
            "{\n\t.reg .pred p;\n\t"
            "mbarrier.try_wait.parity.acquire.cta.shared::cta.b64 p, [%1], %2, 0x989680;\n\t"
            "selp.b32 %0, 1, 0, p;\n\t}"
            : "=r"(done) : "r"(a), "r"(ph) : "memory");
    } while (!done);
}

__global__ void detect_idx_kernel(const int* __restrict__ ei32) {
    if (threadIdx.x == 0 && blockIdx.x == 0) {
        int ornz = 0;
#pragma unroll
        for (int i = 0; i < 64; ++i) ornz |= ei32[2 * i + 1];
        g_is64 = (ornz == 0) ? 1 : 0;
    }
}

// Build fp16 B fragment tables. k0 = 16cs + 2t4; n = 32hn + 8nt + g4.
// qa[nt] = (w[k0][n], w[k0+1][n]); qb[nt] = (w[k0+8][n], w[k0+9][n]).
__global__ void prep_frag_kernel(const float* __restrict__ fw1,
                                 const float* __restrict__ fw2) {
    int i = blockIdx.x * blockDim.x + threadIdx.x;
    int lane = i & 31, hn = (i >> 5) & 1, cs = i >> 6;
    int t4 = lane & 3, g4 = lane >> 2;
    if (cs < 20) {
        int k0 = 16 * cs + 2 * t4;
        uint32_t ra[4], rb[4];
#pragma unroll
        for (int nt = 0; nt < 4; ++nt) {
            int n = 32 * hn + 8 * nt + g4;
            float w00 = (k0 < RK) ? fw1[k0 * 64 + n] : 0.f;
            float w01 = (k0 + 1 < RK) ? fw1[(k0 + 1) * 64 + n] : 0.f;
            float w10 = (k0 + 8 < RK) ? fw1[(k0 + 8) * 64 + n] : 0.f;
            float w11 = (k0 + 9 < RK) ? fw1[(k0 + 9) * 64 + n] : 0.f;
            ra[nt] = pk(w00, w01);
            rb[nt] = pk(w10, w11);
        }
        g_fw1ha[i] = make_uint4(ra[0], ra[1], ra[2], ra[3]);
        g_fw1hb[i] = make_uint4(rb[0], rb[1], rb[2], rb[3]);
    }
    if (cs < 4) {
        int k0 = 16 * cs + 2 * t4;
        uint32_t ra[4], rb[4];
#pragma unroll
        for (int nt = 0; nt < 4; ++nt) {
            int n = 32 * hn + 8 * nt + g4;
            ra[nt] = pk(fw2[k0 * 64 + n], fw2[(k0 + 1) * 64 + n]);
            rb[nt] = pk(fw2[(k0 + 8) * 64 + n], fw2[(k0 + 9) * 64 + n]);
        }
        g_fw2ha[i] = make_uint4(ra[0], ra[1], ra[2], ra[3]);
        g_fw2hb[i] = make_uint4(rb[0], rb[1], rb[2], rb[3]);
    }
}

// ---------------------------------------------------------------------------
// node kernels (proven R6 versions)
// ---------------------------------------------------------------------------
__global__ void __launch_bounds__(256)
node_pre_kernel(const float* __restrict__ x, const float* __restrict__ W,
                const float* __restrict__ b, int N) {
    __shared__ float xs[128 * 64];
    int tid = threadIdx.x;
    int j = tid & 63, q = tid >> 6;
    long n0 = (long)blockIdx.x * 128;
    uint32_t sb = (uint32_t)__cvta_generic_to_shared(xs);
    for (int i = tid; i < 2048; i += 256) {
        long node = n0 + (i >> 4);
        cp16(sb + i * 16, x + node * 64 + (i & 15) * 4, node < N ? 16 : 0);
    }
    cp_commit();
    float Wc[64];
#pragma unroll
    for (int k = 0; k < 64; ++k) Wc[k] = W[k * 64 + j];
    float bj = b[j];
    cp_wait0();
    __syncthreads();
#pragma unroll 4
    for (int nn = 0; nn < 32; ++nn) {
        int r = nn * 4 + q;
        long node = n0 + r;
        float acc = bj;
        const float* xr = xs + r * 64;
#pragma unroll
        for (int k = 0; k < 64; k += 4) {
            float4 xv = *(const float4*)(xr + k);
            acc += xv.x * Wc[k] + xv.y * Wc[k + 1] + xv.z * Wc[k + 2] + xv.w * Wc[k + 3];
        }
        if (node < N) {
            g_h[node * 64 + j] = acc;
            g_agg[node * 64 + j] = 0.f;
        }
    }
}

__global__ void __launch_bounds__(256)
node_post_kernel(const float* __restrict__ x0, const float* __restrict__ W2,
                 const float* __restrict__ b2, const float* __restrict__ W3,
                 const float* __restrict__ b3, float* __restrict__ out, int N) {
    extern __shared__ float smp[];
    float* xs = smp;
    float* ts = smp + 8192;
    int tid = threadIdx.x;
    int j = tid & 63, q = tid >> 6;
    long n0 = (long)blockIdx.x * 128;
    uint32_t sb = (uint32_t)__cvta_generic_to_shared(xs);
    for (int i = tid; i < 2048; i += 256) {
        long node = n0 + (i >> 4);
        cp16(sb + i * 16, g_agg + node * 64 + (i & 15) * 4, node < N ? 16 : 0);
    }
    cp_commit();
    float W2c[64], W3c[64];
#pragma unroll
    for (int k = 0; k < 64; ++k) { W2c[k] = W2[k * 64 + j]; W3c[k] = W3[k * 64 + j]; }
    float b2j = b2[j], b3j = b3[j];
    cp_wait0();
    __syncthreads();
#pragma unroll 4
    for (int nn = 0; nn < 32; ++nn) {
        int r = nn * 4 + q;
        float acc = b2j;
        const float* xr = xs + r * 64;
#pragma unroll
        for (int k = 0; k < 64; k += 4) {
            float4 xv = *(const float4*)(xr + k);
            acc += xv.x * W2c[k] + xv.y * W2c[k + 1] + xv.z * W2c[k + 2] + xv.w * W2c[k + 3];
        }
        ts[r * 64 + j] = sspf(acc);
    }
    __syncthreads();
#pragma unroll 4
    for (int nn = 0; nn < 32; ++nn) {
        int r = nn * 4 + q;
        long node = n0 + r;
        float acc = b3j;
        const float* tr = ts + r * 64;
#pragma unroll
        for (int k = 0; k < 64; k += 4) {
            float4 tv = *(const float4*)(tr + k);
            acc += tv.x * W3c[k] + tv.y * W3c[k + 1] + tv.z * W3c[k + 2] + tv.w * W3c[k + 3];
        }
        if (node < N) out[node * 64 + j] = acc + x0[node * 64 + j];
    }
}

// ---------------------------------------------------------------------------
// edge kernel: R12 skeleton (sequential bulks, stride-300 A), fp16 m16n8k16
// GEMMs (2x tensor throughput vs tf32), packed-fp16 C handoff, f32 w2 stage.
// smem floats:
#define OFF_A   0        // 128 x 300 = 38400 (150KB)
#define OFF_PAD 38400    // 32 floats zero pad
#define OFF_CH  38432    // 128 x 32 uint32 (packed fp16) = 4096 (16KB)
#define OFF_C2  42528    // 128 x 64 f32 = 8192 (32KB)
#define OFF_B1  50720
#define OFF_B2  50784
#define OFF_MB  50848    // 2 mbarriers
#define SMEM_FLOATS 50852
#define CSW(r, c) ((r) * 64 + ((c) ^ (((r) & 7) << 2)))

__global__ void __launch_bounds__(512)
edge_kernel(const float* __restrict__ rbf, const void* __restrict__ ei,
            const float* __restrict__ dist, const float* __restrict__ cutoff,
            const float* __restrict__ fb1, const float* __restrict__ fb2,
            int E, int NT, int GRIDSZ) {
    extern __shared__ __align__(1024) float sm[];
    uint32_t sbase = (uint32_t)__cvta_generic_to_shared(sm);
    uint32_t* CH = (uint32_t*)(sm + OFF_CH);
    int tid = threadIdx.x, lane = tid & 31, warp = tid >> 5;
    int t4 = lane & 3, g4 = lane >> 2;
    int hn = warp & 1, rw = (warp >> 1) * 16;
    uint32_t mb0 = sbase + OFF_MB * 4, mb1 = mb0 + 8;
    uint32_t mymb = (rw >= 64) ? mb1 : mb0;

    for (int i = tid; i < 38432; i += 512) sm[i] = 0.f;
    if (tid < 64) { sm[OFF_B1 + tid] = fb1[tid]; sm[OFF_B2 + tid] = fb2[tid]; }
    if (tid == 0) { mbar_init(mb0, 1); mbar_init(mb1, 1); }
    __syncthreads();

    int is64 = g_is64;
    float picf = 3.14159265f / (*cutoff);

    auto issue = [&](long t) {
        if (t >= (long)NT) return;
        long e0 = t * TILE;
        int V = (int)((long)E - e0 < TILE ? (long)E - e0 : TILE);
        int V0 = V < 64 ? V : 64;
        int V1 = V - V0;
        mbar_expect(mb0, (uint32_t)(V0 * 1200));
        bulk_g2s(sbase + OFF_A * 4, rbf + e0 * 300, V0 * 1200, mb0);
        mbar_expect(mb1, (uint32_t)(V1 * 1200));
        if (V1 > 0)
            bulk_g2s(sbase + (OFF_A + 64 * 300) * 4, rbf + (e0 + 64) * 300,
                     V1 * 1200, mb1);
    };
    if (tid == 0) issue(blockIdx.x);
    int ph = 0;

    int el = tid >> 2, qr = tid & 3;
    int r0 = rw + g4, sw = g4 << 2;

    for (long tile = blockIdx.x; tile < (long)NT; tile += GRIDSZ) {
        long e0 = tile * TILE;

        // epilogue index/dist preload (overlaps bulk-load wait)
        long e = e0 + el;
        long long dstn = 0, srcn = 0;
        float f = 0.f;
        if (e < (long)E) {
            if (is64) {
                const long long* pp = (const long long*)ei;
                dstn = pp[e]; srcn = pp[(long)E + e];
            } else {
                const int* pp = (const int*)ei;
                dstn = pp[e]; srcn = pp[(long)E + e];
            }
            dstn = dstn < 0 ? 0 : (dstn >= NMAX ? NMAX - 1 : dstn);
            srcn = srcn < 0 ? 0 : (srcn >= NMAX ? NMAX - 1 : srcn);
            f = 1.f + __cosf(picf * dist[e]);
        }

        // ---- GEMM1: fp16 m16n8k16, 20 k-steps, K resident ----
        mbar_wait(mymb, ph);
        float acc[4][4];
#pragma unroll
        for (int t = 0; t < 4; ++t)
#pragma unroll
            for (int jj = 0; jj < 4; ++jj) acc[t][jj] = 0.f;

        const float* Ar0 = sm + OFF_A + r0 * 300 + 2 * t4;
        const float* Ar1 = Ar0 + 8 * 300;
        const uint4* Ba = g_fw1ha + hn * 32 + lane;
        const uint4* Bb = g_fw1hb + hn * 32 + lane;
        uint4 qa = __ldg(Ba), qb = __ldg(Bb);
#pragma unroll
        for (int cs = 0; cs < 20; ++cs) {
            uint4 na, nb;
            if (cs < 19) { na = __ldg(Ba + (cs + 1) * 64); nb = __ldg(Bb + (cs + 1) * 64); }
            float2 p0 = *(const float2*)(Ar0 + 16 * cs);
            float2 p1 = *(const float2*)(Ar1 + 16 * cs);
            float2 p2 = *(const float2*)(Ar0 + 16 * cs + 8);
            float2 p3 = *(const float2*)(Ar1 + 16 * cs + 8);
            uint32_t a0 = pk(p0.x, p0.y), a1 = pk(p1.x, p1.y);
            uint32_t a2 = pk(p2.x, p2.y), a3 = pk(p3.x, p3.y);
            mma_f16(acc[0], a0, a1, a2, a3, qa.x, qb.x);
            mma_f16(acc[1], a0, a1, a2, a3, qa.y, qb.y);
            mma_f16(acc[2], a0, a1, a2, a3, qa.z, qb.z);
            mma_f16(acc[3], a0, a1, a2, a3, qa.w, qb.w);
            qa = na; qb = nb;
        }

        // bias + ssp -> packed fp16 C (XOR-swizzled words)
#pragma unroll
        for (int nt = 0; nt < 4; ++nt) {
            int cb = 32 * hn + 8 * nt + 2 * t4;
            float b0v = sm[OFF_B1 + cb], b1v = sm[OFF_B1 + cb + 1];
            int wd = (cb >> 1) ^ sw;
            CH[r0 * 32 + wd] = pk(sspf(acc[nt][0] + b0v), sspf(acc[nt][1] + b1v));
            CH[(r0 + 8) * 32 + wd] = pk(sspf(acc[nt][2] + b0v), sspf(acc[nt][3] + b1v));
        }
        __syncthreads();                      // (1) C1 ready; A consumed

        if (tid == 0) issue(tile + GRIDSZ);   // next tile's sequential bulks

        // ---- GEMM2: fp16, A from packed C, 4 k-steps ----
        float acc2[4][4];
#pragma unroll
        for (int t = 0; t < 4; ++t)
#pragma unroll
            for (int jj = 0; jj < 4; ++jj) acc2[t][jj] = 0.f;
        const uint4* B2a = g_fw2ha + hn * 32 + lane;
        const uint4* B2b = g_fw2hb + hn * 32 + lane;
#pragma unroll
        for (int cs = 0; cs < 4; ++cs) {
            uint32_t a0 = CH[r0 * 32 + ((8 * cs + t4) ^ sw)];
            uint32_t a1 = CH[(r0 + 8) * 32 + ((8 * cs + t4) ^ sw)];
            uint32_t a2 = CH[r0 * 32 + ((8 * cs + 4 + t4) ^ sw)];
            uint32_t a3 = CH[(r0 + 8) * 32 + ((8 * cs + 4 + t4) ^ sw)];
            uint4 q2a = __ldg(B2a + cs * 64), q2b = __ldg(B2b + cs * 64);
            mma_f16(acc2[0], a0, a1, a2, a3, q2a.x, q2b.x);
            mma_f16(acc2[1], a0, a1, a2, a3, q2a.y, q2b.y);
            mma_f16(acc2[2], a0, a1, a2, a3, q2a.z, q2b.z);
            mma_f16(acc2[3], a0, a1, a2, a3, q2a.w, q2b.w);
        }

        // bias + ssp -> f32 w2 stage (CSW) for epilogue precision
#pragma unroll
        for (int nt = 0; nt < 4; ++nt) {
            int cb = 32 * hn + 8 * nt + 2 * t4;
            float b0v = sm[OFF_B2 + cb], b1v = sm[OFF_B2 + cb + 1];
            *(float2*)&sm[OFF_C2 + CSW(r0, cb)] =
                make_float2(sspf(acc2[nt][0] + b0v), sspf(acc2[nt][1] + b1v));
            *(float2*)&sm[OFF_C2 + CSW(r0 + 8, cb)] =
                make_float2(sspf(acc2[nt][2] + b0v), sspf(acc2[nt][3] + b1v));
        }
        __syncthreads();                      // (2) w2 ready

        // epilogue: gather h[src], scatter atomics into agg[dst]
        if (e < (long)E) {
            const float* hrow = g_h + (long)srcn * 64 + qr * 16;
            float* arow = g_agg + (long)dstn * 64 + qr * 16;
#pragma unroll
            for (int jj = 0; jj < 4; ++jj) {
                float4 w = *(const float4*)&sm[OFF_C2 + CSW(el, qr * 16 + 4 * jj)];
                float4 h4 = *(const float4*)(hrow + 4 * jj);
                atomicAdd((float4*)(arow + 4 * jj),
                          make_float4(w.x * h4.x * f, w.y * h4.y * f,
                                      w.z * h4.z * f, w.w * h4.w * f));
            }
        }
        __syncthreads();                      // (3) buffers free
        ph ^= 1;
    }
}

// ---------------------------------------------------------------------------
extern "C" void kernel_launch(void* const* d_in, const int* in_sizes, int n_in,
                              void* d_out, int out_size) {
    const void* ei       = d_in[0];
    const float* x       = (const float*)d_in[1];
    const float* rbf     = (const float*)d_in[2];
    const float* dist    = (const float*)d_in[3];
    const float* cutoff  = (const float*)d_in[4];
    const float* fw1     = (const float*)d_in[5];
    const float* fb1     = (const float*)d_in[6];
    const float* fw2     = (const float*)d_in[7];
    const float* fb2     = (const float*)d_in[8];
    const float* l1w     = (const float*)d_in[9];
    const float* l1b     = (const float*)d_in[10];
    const float* l2w     = (const float*)d_in[11];
    const float* l2b     = (const float*)d_in[12];
    const float* l3w     = (const float*)d_in[13];
    const float* l3b     = (const float*)d_in[14];

    int E = in_sizes[0] / 2;
    int N = in_sizes[1] / 64;
    int NT = (E + TILE - 1) / TILE;
    int NB = (N + 127) / 128;

    static int sms = 0;
    if (!sms) cudaDeviceGetAttribute(&sms, cudaDevAttrMultiProcessorCount, 0);
    int grid = sms > 0 ? sms : 148;
    if (grid > NT) grid = NT;

    cudaFuncSetAttribute(edge_kernel, cudaFuncAttributeMaxDynamicSharedMemorySize,
                         SMEM_FLOATS * 4);
    cudaFuncSetAttribute(node_post_kernel, cudaFuncAttributeMaxDynamicSharedMemorySize,
                         65536);

    detect_idx_kernel<<<1, 32>>>((const int*)ei);
    prep_frag_kernel<<<(20 * 2 * 32 + 255) / 256, 256>>>(fw1, fw2);
    node_pre_kernel<<<NB, 256>>>(x, l1w, l1b, N);
    edge_kernel<<<grid, 512, SMEM_FLOATS * 4>>>(rbf, ei, dist, cutoff,
                                                fb1, fb2, E, NT, grid);
    node_post_kernel<<<NB, 256, 65536>>>(x, l2w, l2b, l3w, l3b, (float*)d_out, N);
}